// round 1
// baseline (speedup 1.0000x reference)
#include <cuda_runtime.h>
#include <cuda_bf16.h>
#include <cstdint>

// 3x3 stride-1 pad-1 conv, NCHW fp32. B=8, CIN=COUT=16, H=W=1024.
// Strategy: FFMA2 (packed f32x2) direct conv.
//   - block = 256 threads = one (b, h) output row; each thread: 4 px * 16 cout.
//   - weights in smem, duplicated (w,w) pairs, layout [cin][kh][kw][cout].
//   - x loaded from gmem (float4 + 2 halo scalars), predicated zero-padding.

#define B_   8
#define CIN_ 16
#define COUT_ 16
#define H_   1024
#define W_   1024

__device__ __forceinline__ unsigned long long fma2(unsigned long long a,
                                                   unsigned long long b,
                                                   unsigned long long c) {
    unsigned long long d;
    asm("fma.rn.f32x2 %0, %1, %2, %3;" : "=l"(d) : "l"(a), "l"(b), "l"(c));
    return d;
}

__device__ __forceinline__ unsigned long long pack2(float lo, float hi) {
    unsigned long long d;
    asm("mov.b64 %0, {%1, %2};" : "=l"(d) : "f"(lo), "f"(hi));
    return d;
}

__device__ __forceinline__ void unpack2(unsigned long long v, float& lo, float& hi) {
    asm("mov.b64 {%0, %1}, %2;" : "=f"(lo), "=f"(hi) : "l"(v));
}

__global__ __launch_bounds__(256) void conv3x3_f32x2_kernel(
    const float* __restrict__ x,
    const float* __restrict__ Wt,   // [COUT][CIN][3][3]
    float* __restrict__ out)
{
    // Duplicated weight pairs: ws[((cin*3+kh)*3+kw)*16 + co] = (w, w)
    __shared__ __align__(16) float2 ws[CIN_ * 3 * 3 * COUT_];  // 2304 float2 = 18.4 KB

    const int t = threadIdx.x;
    const int h = blockIdx.x;
    const int b = blockIdx.y;
    const int ow0 = t * 4;

    // Cooperative weight load + transpose + duplicate.
    // Wt linear index i = co*144 + (cin*9 + kh*3 + kw) = co*144 + r
    for (int i = t; i < COUT_ * CIN_ * 9; i += 256) {
        int co = i / (CIN_ * 9);
        int r  = i - co * (CIN_ * 9);
        float w = Wt[i];
        ws[r * COUT_ + co] = make_float2(w, w);
    }
    __syncthreads();

    unsigned long long acc0[COUT_];  // pixels (0,1)
    unsigned long long acc1[COUT_];  // pixels (2,3)
#pragma unroll
    for (int co = 0; co < COUT_; co++) { acc0[co] = 0ull; acc1[co] = 0ull; }

    const float* xb = x + (size_t)b * CIN_ * H_ * W_;

#pragma unroll 1
    for (int cin = 0; cin < CIN_; cin++) {
        const float* xplane = xb + (size_t)cin * H_ * W_;
#pragma unroll
        for (int kh = 0; kh < 3; kh++) {
            int ih = h + kh - 1;
            bool rv = ((unsigned)ih < (unsigned)H_);   // warp-uniform
            float4 xm = make_float4(0.f, 0.f, 0.f, 0.f);
            float xl = 0.f, xr = 0.f;
            if (rv) {
                const float* row = xplane + (size_t)ih * W_;
                xm = *reinterpret_cast<const float4*>(row + ow0);
                if (t > 0)   xl = __ldg(row + ow0 - 1);
                if (t < 255) xr = __ldg(row + ow0 + 4);
            }
            // shifted pairs for kw = 0(-1), 1(0), 2(+1)
            unsigned long long pA0 = pack2(xl,   xm.x);  // kw=0, px(0,1)
            unsigned long long pA1 = pack2(xm.y, xm.z);  // kw=0, px(2,3)  (== kw=2 px(0,1))
            unsigned long long pB0 = pack2(xm.x, xm.y);  // kw=1, px(0,1)
            unsigned long long pB1 = pack2(xm.z, xm.w);  // kw=1, px(2,3)
            unsigned long long pC0 = pA1;                // kw=2, px(0,1)
            unsigned long long pC1 = pack2(xm.w, xr);    // kw=2, px(2,3)

            const int wbase = ((cin * 3 + kh) * 3) * COUT_;
#pragma unroll
            for (int kw = 0; kw < 3; kw++) {
                unsigned long long a0 = (kw == 0) ? pA0 : (kw == 1) ? pB0 : pC0;
                unsigned long long a1 = (kw == 0) ? pA1 : (kw == 1) ? pB1 : pC1;
                const ulonglong2* wq =
                    reinterpret_cast<const ulonglong2*>(&ws[wbase + kw * COUT_]);
#pragma unroll
                for (int j = 0; j < 8; j++) {
                    ulonglong2 wv = wq[j];       // 2 couts' (w,w) pairs, LDS.128 broadcast
                    int c0 = 2 * j, c1 = 2 * j + 1;
                    acc0[c0] = fma2(a0, wv.x, acc0[c0]);
                    acc1[c0] = fma2(a1, wv.x, acc1[c0]);
                    acc0[c1] = fma2(a0, wv.y, acc0[c1]);
                    acc1[c1] = fma2(a1, wv.y, acc1[c1]);
                }
            }
        }
    }

    // Epilogue: 16 STG.128
    float* ob = out + (size_t)b * COUT_ * H_ * W_ + (size_t)h * W_ + ow0;
#pragma unroll
    for (int co = 0; co < COUT_; co++) {
        float o0, o1, o2, o3;
        unpack2(acc0[co], o0, o1);
        unpack2(acc1[co], o2, o3);
        *reinterpret_cast<float4*>(ob + (size_t)co * H_ * W_) =
            make_float4(o0, o1, o2, o3);
    }
}

extern "C" void kernel_launch(void* const* d_in, const int* in_sizes, int n_in,
                              void* d_out, int out_size) {
    const float* x  = (const float*)d_in[0];
    const float* Wt = (const float*)d_in[1];
    // Defensive: identify weight tensor by its size (2304 elements).
    if (n_in >= 2 && in_sizes[0] == COUT_ * CIN_ * 9) {
        const float* tmp = x; x = Wt; Wt = tmp;
    }
    float* out = (float*)d_out;

    dim3 grid(H_, B_);
    conv3x3_f32x2_kernel<<<grid, 256>>>(x, Wt, out);
}

// round 5
// speedup vs baseline: 1.7848x; 1.7848x over previous
#include <cuda_runtime.h>
#include <cuda_bf16.h>
#include <cstdint>

// 3x3 s1 p1 conv, NCHW fp32, B=8 C=16 H=W=1024.
// Warp-level HMMA (mma.sync m16n8k16 bf16) implicit GEMM, 3-term bf16 split:
//   D = Ah*Bh + Al*Bh + Ah*Bl   (Al*Bl ~2^-16, dropped)
// X staged in smem sliding window: [row][pixel][16cin bf16 hi(32B) | lo(32B)]
// pixel slot stride 80B => ldmatrix 8-row phases are bank-conflict-free.
// kw shift = +1 slot, kh = +1 row: A fragments read in place, no im2col.

#define B_   8
#define H_   1024
#define Wd_  1024
#define TH   4
#define TW   128
#define NR   (TH + 2)     // 6 input rows
#define RW   (TW + 2)     // 130 pixel slots per row
#define SLOT 80           // bytes per pixel slot (64 used)
#define XS_BYTES (NR * RW * SLOT)          // 62400
#define WF_OFF   XS_BYTES
#define WF_BYTES (9 * 2 * 2 * 32 * 8)      // 9216 (tap,bt,nc,lane -> uint2)
#define SMEM_BYTES (XS_BYTES + WF_BYTES)   // 71616

__device__ __forceinline__ uint32_t smem_u32(const void* p) {
    uint32_t a;
    asm("{ .reg .u64 t; cvta.to.shared.u64 t, %1; cvt.u32.u64 %0, t; }"
        : "=r"(a) : "l"(p));
    return a;
}

__device__ __forceinline__ void ldm4(uint32_t* a, uint32_t addr) {
    asm volatile("ldmatrix.sync.aligned.m8n8.x4.shared.b16 {%0,%1,%2,%3}, [%4];"
                 : "=r"(a[0]), "=r"(a[1]), "=r"(a[2]), "=r"(a[3]) : "r"(addr));
}

__device__ __forceinline__ void mma16816(float* d, const uint32_t* a, uint2 b) {
    asm volatile(
        "mma.sync.aligned.m16n8k16.row.col.f32.bf16.bf16.f32 "
        "{%0,%1,%2,%3}, {%4,%5,%6,%7}, {%8,%9}, {%0,%1,%2,%3};"
        : "+f"(d[0]), "+f"(d[1]), "+f"(d[2]), "+f"(d[3])
        : "r"(a[0]), "r"(a[1]), "r"(a[2]), "r"(a[3]), "r"(b.x), "r"(b.y));
}

__device__ __forceinline__ uint32_t pk(__nv_bfloat16 a, __nv_bfloat16 b) {
    return ((uint32_t)__bfloat16_as_ushort(b) << 16) |
           (uint32_t)__bfloat16_as_ushort(a);
}

__global__ __launch_bounds__(256) void conv3x3_hmma_kernel(
    const float* __restrict__ x,
    const float* __restrict__ Wt,   // [16co][16cin][3][3]
    float* __restrict__ out)
{
    extern __shared__ __align__(128) char smem[];
    const int tid = threadIdx.x, wid = tid >> 5, lid = tid & 31;
    const int w0 = blockIdx.x * TW, h0 = blockIdx.y * TH, b = blockIdx.z;

    // ---- stage X: fp32 -> bf16 hi/lo, [row][px][cin] ----
    const float* xb = x + (size_t)b * 16 * H_ * Wd_;
    for (int e = tid; e < NR * RW * 16; e += 256) {
        int px  = e % RW;
        int rc  = e / RW;
        int cin = rc & 15;
        int row = rc >> 4;
        int ih = h0 - 1 + row;
        int iw = w0 - 1 + px;
        float v = 0.f;
        if ((unsigned)ih < (unsigned)H_ && (unsigned)iw < (unsigned)Wd_)
            v = xb[((size_t)cin * H_ + ih) * Wd_ + iw];
        __nv_bfloat16 hi = __float2bfloat16(v);
        __nv_bfloat16 lo = __float2bfloat16(v - __bfloat162float(hi));
        char* p = smem + (row * RW + px) * SLOT + cin * 2;
        *(__nv_bfloat16*)p        = hi;
        *(__nv_bfloat16*)(p + 32) = lo;
    }

    // ---- weights -> per-lane B fragments: [tap][bt][nc][lane] uint2 ----
    // B frag (m16n8k16 col): b0 = B[k0..k0+1][n], b1 = B[k0+8..k0+9][n],
    //   n = lane>>2 (+8*nc), k0 = 2*(lane&3).
    uint2* wf = (uint2*)(smem + WF_OFF);
    for (int c = wid; c < 18; c += 8) {
        int tap = c >> 1, nc = c & 1;
        int co = nc * 8 + (lid >> 2);
        int k0 = 2 * (lid & 3);
        float w00 = Wt[co * 144 + k0 * 9 + tap];
        float w01 = Wt[co * 144 + (k0 + 1) * 9 + tap];
        float w10 = Wt[co * 144 + (k0 + 8) * 9 + tap];
        float w11 = Wt[co * 144 + (k0 + 9) * 9 + tap];
        __nv_bfloat16 h00 = __float2bfloat16(w00), h01 = __float2bfloat16(w01);
        __nv_bfloat16 h10 = __float2bfloat16(w10), h11 = __float2bfloat16(w11);
        __nv_bfloat16 l00 = __float2bfloat16(w00 - __bfloat162float(h00));
        __nv_bfloat16 l01 = __float2bfloat16(w01 - __bfloat162float(h01));
        __nv_bfloat16 l10 = __float2bfloat16(w10 - __bfloat162float(h10));
        __nv_bfloat16 l11 = __float2bfloat16(w11 - __bfloat162float(h11));
        wf[((tap * 2 + 0) * 2 + nc) * 32 + lid] = make_uint2(pk(h00, h01), pk(h10, h11));
        wf[((tap * 2 + 1) * 2 + nc) * 32 + lid] = make_uint2(pk(l00, l01), pk(l10, l11));
    }
    __syncthreads();

    // ---- compute: warp -> (row r, w-segment), 4 m16 tiles each ----
    const uint32_t xs = smem_u32(smem);
    const int r = wid >> 1, wseg = wid & 1;

    // ldmatrix lane addressing: mat = lid>>3
    //   mat0: rows 0-7 k0-7 | mat1: rows 8-15 k0-7 | mat2/3: +16B (k8-15)
    const int mat  = lid >> 3;
    const int arow = (mat & 1) * 8 + (lid & 7);
    const int kofs = (mat >> 1) * 16;

    for (int mt = 0; mt < 4; mt++) {
        const int ol0 = wseg * 64 + mt * 16;
        float acc[2][4] = {{0.f, 0.f, 0.f, 0.f}, {0.f, 0.f, 0.f, 0.f}};

#pragma unroll
        for (int kh = 0; kh < 3; kh++) {
#pragma unroll
            for (int kw = 0; kw < 3; kw++) {
                const int tap = kh * 3 + kw;
                uint32_t abase =
                    xs + (uint32_t)(((r + kh) * RW + ol0 + kw + arow) * SLOT + kofs);
                uint32_t ah[4], al[4];
                ldm4(ah, abase);
                ldm4(al, abase + 32);
#pragma unroll
                for (int nc = 0; nc < 2; nc++) {
                    uint2 bh = wf[((tap * 2 + 0) * 2 + nc) * 32 + lid];
                    uint2 bl = wf[((tap * 2 + 1) * 2 + nc) * 32 + lid];
                    mma16816(acc[nc], ah, bh);
                    mma16816(acc[nc], al, bh);
                    mma16816(acc[nc], ah, bl);
                }
            }
        }

        // ---- epilogue: D frag -> gmem ----
        // c0:(row,col) c1:(row,col+1) c2:(row+8,col) c3:(row+8,col+1)
        const int h = h0 + r;
        const int rowp = lid >> 2, col2 = 2 * (lid & 3);
        const int w = w0 + ol0 + rowp;
#pragma unroll
        for (int nc = 0; nc < 2; nc++) {
            int co = nc * 8 + col2;
            size_t base = (((size_t)b * 16 + co) * H_ + h) * Wd_ + w;
            out[base]                       = acc[nc][0];
            out[base + (size_t)H_ * Wd_]     = acc[nc][1];
            out[base + 8]                   = acc[nc][2];
            out[base + (size_t)H_ * Wd_ + 8] = acc[nc][3];
        }
    }
}

extern "C" void kernel_launch(void* const* d_in, const int* in_sizes, int n_in,
                              void* d_out, int out_size) {
    const float* x  = (const float*)d_in[0];
    const float* Wt = (const float*)d_in[1];
    if (n_in >= 2 && in_sizes[0] == 16 * 16 * 9) {
        const float* tmp = x; x = Wt; Wt = tmp;
    }
    float* out = (float*)d_out;

    cudaFuncSetAttribute(conv3x3_hmma_kernel,
                         cudaFuncAttributeMaxDynamicSharedMemorySize, SMEM_BYTES);
    dim3 grid(Wd_ / TW, H_ / TH, B_);
    conv3x3_hmma_kernel<<<grid, 256, SMEM_BYTES>>>(x, Wt, out);
}

// round 7
// speedup vs baseline: 1.8998x; 1.0645x over previous
#include <cuda_runtime.h>
#include <cuda_bf16.h>
#include <cstdint>

// 3x3 s1 p1 conv, NCHW fp32, B=8 C=16 H=W=1024.
// Warp-level HMMA (mma.sync m16n8k16 bf16) implicit GEMM, 3-term bf16 split:
//   D = Ah*Bh + Al*Bh + Ah*Bl
// X staged in smem sliding window: [row][pixel][16cin bf16 hi(32B) | lo(32B)]
// slot stride 80B => ldmatrix / STS.128 8-row phases are bank-conflict-free.
// R6: tap-outer loop (B frags loaded once per tap), vectorized STS.128 staging.

#define B_   8
#define H_   1024
#define Wd_  1024
#define TH   4
#define TW   128
#define NR   (TH + 2)     // 6 input rows
#define RW   (TW + 2)     // 130 pixel slots per row
#define SLOT 80           // bytes per pixel slot (64 used)
#define XS_BYTES (NR * RW * SLOT)          // 62400
#define WF_OFF   XS_BYTES
#define WF_BYTES (9 * 2 * 2 * 32 * 8)      // 9216 (tap,bt,nc,lane -> uint2)
#define SMEM_BYTES (XS_BYTES + WF_BYTES)   // 71616

__device__ __forceinline__ uint32_t smem_u32(const void* p) {
    uint32_t a;
    asm("{ .reg .u64 t; cvta.to.shared.u64 t, %1; cvt.u32.u64 %0, t; }"
        : "=r"(a) : "l"(p));
    return a;
}

__device__ __forceinline__ void ldm4(uint32_t* a, uint32_t addr) {
    asm volatile("ldmatrix.sync.aligned.m8n8.x4.shared.b16 {%0,%1,%2,%3}, [%4];"
                 : "=r"(a[0]), "=r"(a[1]), "=r"(a[2]), "=r"(a[3]) : "r"(addr));
}

__device__ __forceinline__ void mma16816(float* d, const uint32_t* a, uint2 b) {
    asm volatile(
        "mma.sync.aligned.m16n8k16.row.col.f32.bf16.bf16.f32 "
        "{%0,%1,%2,%3}, {%4,%5,%6,%7}, {%8,%9}, {%0,%1,%2,%3};"
        : "+f"(d[0]), "+f"(d[1]), "+f"(d[2]), "+f"(d[3])
        : "r"(a[0]), "r"(a[1]), "r"(a[2]), "r"(a[3]), "r"(b.x), "r"(b.y));
}

__device__ __forceinline__ uint32_t pk(__nv_bfloat16 a, __nv_bfloat16 b) {
    return ((uint32_t)__bfloat16_as_ushort(b) << 16) |
           (uint32_t)__bfloat16_as_ushort(a);
}

__device__ __forceinline__ uint32_t pkf(float a, float b) {
    return pk(__float2bfloat16(a), __float2bfloat16(b));
}

__global__ __launch_bounds__(256, 3) void conv3x3_hmma_kernel(
    const float* __restrict__ x,
    const float* __restrict__ Wt,   // [16co][16cin][3][3]
    float* __restrict__ out)
{
    extern __shared__ __align__(128) char smem[];
    const int tid = threadIdx.x, wid = tid >> 5, lid = tid & 31;
    const int w0 = blockIdx.x * TW, h0 = blockIdx.y * TH, b = blockIdx.z;

    // ---- stage X: one thread per pixel, 16 LDG.32 -> 4x STS.128 ----
    const float* xb = x + (size_t)b * 16 * H_ * Wd_;
    for (int p = tid; p < NR * RW; p += 256) {
        const int row = p / RW, px = p - row * RW;
        const int ih = h0 - 1 + row, iw = w0 - 1 + px;
        const bool valid = ((unsigned)ih < (unsigned)H_) &&
                           ((unsigned)iw < (unsigned)Wd_);
        float v[16];
#pragma unroll
        for (int c = 0; c < 16; c++)
            v[c] = valid ? xb[((size_t)c * H_ + ih) * Wd_ + iw] : 0.f;

        float l[16];
#pragma unroll
        for (int c = 0; c < 16; c++)
            l[c] = v[c] - __bfloat162float(__float2bfloat16(v[c]));

        uint4 hA = make_uint4(pkf(v[0], v[1]),  pkf(v[2], v[3]),
                              pkf(v[4], v[5]),  pkf(v[6], v[7]));
        uint4 hB = make_uint4(pkf(v[8], v[9]),  pkf(v[10], v[11]),
                              pkf(v[12], v[13]), pkf(v[14], v[15]));
        uint4 lA = make_uint4(pkf(l[0], l[1]),  pkf(l[2], l[3]),
                              pkf(l[4], l[5]),  pkf(l[6], l[7]));
        uint4 lB = make_uint4(pkf(l[8], l[9]),  pkf(l[10], l[11]),
                              pkf(l[12], l[13]), pkf(l[14], l[15]));
        char* s = smem + p * SLOT;
        *(uint4*)(s)      = hA;
        *(uint4*)(s + 16) = hB;
        *(uint4*)(s + 32) = lA;
        *(uint4*)(s + 48) = lB;
    }

    // ---- weights -> per-lane B fragments: [tap][bt][nc][lane] uint2 ----
    uint2* wf = (uint2*)(smem + WF_OFF);
    for (int c = wid; c < 18; c += 8) {
        int tap = c >> 1, nc = c & 1;
        int co = nc * 8 + (lid >> 2);
        int k0 = 2 * (lid & 3);
        float w00 = Wt[co * 144 + k0 * 9 + tap];
        float w01 = Wt[co * 144 + (k0 + 1) * 9 + tap];
        float w10 = Wt[co * 144 + (k0 + 8) * 9 + tap];
        float w11 = Wt[co * 144 + (k0 + 9) * 9 + tap];
        __nv_bfloat16 h00 = __float2bfloat16(w00), h01 = __float2bfloat16(w01);
        __nv_bfloat16 h10 = __float2bfloat16(w10), h11 = __float2bfloat16(w11);
        __nv_bfloat16 l00 = __float2bfloat16(w00 - __bfloat162float(h00));
        __nv_bfloat16 l01 = __float2bfloat16(w01 - __bfloat162float(h01));
        __nv_bfloat16 l10 = __float2bfloat16(w10 - __bfloat162float(h10));
        __nv_bfloat16 l11 = __float2bfloat16(w11 - __bfloat162float(h11));
        wf[((tap * 2 + 0) * 2 + nc) * 32 + lid] = make_uint2(pk(h00, h01), pk(h10, h11));
        wf[((tap * 2 + 1) * 2 + nc) * 32 + lid] = make_uint2(pk(l00, l01), pk(l10, l11));
    }
    __syncthreads();

    // ---- compute: warp -> (row r, w-segment); tap outer, 4 m16 tiles inner ----
    const uint32_t xs = smem_u32(smem);
    const int r = wid >> 1, wseg = wid & 1;

    const int mat  = lid >> 3;
    const int arow = (mat & 1) * 8 + (lid & 7);
    const int kofs = (mat >> 1) * 16;

    float acc[4][2][4];
#pragma unroll
    for (int mt = 0; mt < 4; mt++)
#pragma unroll
        for (int nc = 0; nc < 2; nc++)
#pragma unroll
            for (int i = 0; i < 4; i++) acc[mt][nc][i] = 0.f;

#pragma unroll
    for (int kh = 0; kh < 3; kh++) {
#pragma unroll
        for (int kw = 0; kw < 3; kw++) {
            const int tap = kh * 3 + kw;
            const uint2 bh0 = wf[((tap * 2 + 0) * 2 + 0) * 32 + lid];
            const uint2 bh1 = wf[((tap * 2 + 0) * 2 + 1) * 32 + lid];
            const uint2 bl0 = wf[((tap * 2 + 1) * 2 + 0) * 32 + lid];
            const uint2 bl1 = wf[((tap * 2 + 1) * 2 + 1) * 32 + lid];
            const uint32_t abase =
                xs + (uint32_t)(((r + kh) * RW + wseg * 64 + kw + arow) * SLOT + kofs);
#pragma unroll
            for (int mt = 0; mt < 4; mt++) {
                uint32_t ah[4], al[4];
                uint32_t aa = abase + (uint32_t)(mt * 16 * SLOT);
                ldm4(ah, aa);
                ldm4(al, aa + 32);
                mma16816(acc[mt][0], ah, bh0);
                mma16816(acc[mt][0], al, bh0);
                mma16816(acc[mt][0], ah, bl0);
                mma16816(acc[mt][1], ah, bh1);
                mma16816(acc[mt][1], al, bh1);
                mma16816(acc[mt][1], ah, bl1);
            }
        }
    }

    // ---- epilogue ----
    const int h = h0 + r;
    const int rowp = lid >> 2, col2 = 2 * (lid & 3);
#pragma unroll
    for (int mt = 0; mt < 4; mt++) {
        const int w = w0 + wseg * 64 + mt * 16 + rowp;
#pragma unroll
        for (int nc = 0; nc < 2; nc++) {
            int co = nc * 8 + col2;
            size_t base = (((size_t)b * 16 + co) * H_ + h) * Wd_ + w;
            out[base]                        = acc[mt][nc][0];
            out[base + (size_t)H_ * Wd_]     = acc[mt][nc][1];
            out[base + 8]                    = acc[mt][nc][2];
            out[base + (size_t)H_ * Wd_ + 8] = acc[mt][nc][3];
        }
    }
}

extern "C" void kernel_launch(void* const* d_in, const int* in_sizes, int n_in,
                              void* d_out, int out_size) {
    const float* x  = (const float*)d_in[0];
    const float* Wt = (const float*)d_in[1];
    if (n_in >= 2 && in_sizes[0] == 16 * 16 * 9) {
        const float* tmp = x; x = Wt; Wt = tmp;
    }
    float* out = (float*)d_out;

    cudaFuncSetAttribute(conv3x3_hmma_kernel,
                         cudaFuncAttributeMaxDynamicSharedMemorySize, SMEM_BYTES);
    dim3 grid(Wd_ / TW, H_ / TH, B_);
    conv3x3_hmma_kernel<<<grid, 256, SMEM_BYTES>>>(x, Wt, out);
}

// round 10
// speedup vs baseline: 2.9443x; 1.5498x over previous
#include <cuda_runtime.h>
#include <cuda_fp16.h>
#include <cstdint>

// 3x3 s1 p1 conv, NCHW fp32, B=8 C=16 H=W=1024.
// Warp-level HMMA (mma.sync m16n8k16 f16, fp32 accum) implicit GEMM,
// SINGLE-pass fp16 (no hi/lo split): rounding rel-err ~2e-4 << 1e-3.
// X staged in smem sliding window: [row][pixel][16cin fp16 = 32B], slot 48B
// => ldmatrix / STS.128 8-row phases are bank-conflict-free (stride 48 = 12 banks).
// kw shift = +1 slot, kh = +1 row: A fragments read in place, no im2col.

#define B_   8
#define H_   1024
#define Wd_  1024
#define TH   4
#define TW   128
#define NR   (TH + 2)     // 6 input rows
#define RW   (TW + 2)     // 130 pixel slots per row
#define SLOT 48           // bytes per pixel slot (32 used)
#define XS_BYTES (NR * RW * SLOT)          // 37440
#define WF_OFF   XS_BYTES
#define WF_BYTES (9 * 2 * 32 * 8)          // 4608 (tap,nc,lane -> uint2)
#define SMEM_BYTES (XS_BYTES + WF_BYTES)   // 42048

__device__ __forceinline__ uint32_t smem_u32(const void* p) {
    uint32_t a;
    asm("{ .reg .u64 t; cvta.to.shared.u64 t, %1; cvt.u32.u64 %0, t; }"
        : "=r"(a) : "l"(p));
    return a;
}

__device__ __forceinline__ void ldm4(uint32_t* a, uint32_t addr) {
    asm volatile("ldmatrix.sync.aligned.m8n8.x4.shared.b16 {%0,%1,%2,%3}, [%4];"
                 : "=r"(a[0]), "=r"(a[1]), "=r"(a[2]), "=r"(a[3]) : "r"(addr));
}

__device__ __forceinline__ void mma16816(float* d, const uint32_t* a, uint2 b) {
    asm volatile(
        "mma.sync.aligned.m16n8k16.row.col.f32.f16.f16.f32 "
        "{%0,%1,%2,%3}, {%4,%5,%6,%7}, {%8,%9}, {%0,%1,%2,%3};"
        : "+f"(d[0]), "+f"(d[1]), "+f"(d[2]), "+f"(d[3])
        : "r"(a[0]), "r"(a[1]), "r"(a[2]), "r"(a[3]), "r"(b.x), "r"(b.y));
}

__device__ __forceinline__ uint32_t pkf(float a, float b) {
    __half2 h = __floats2half2_rn(a, b);
    return *reinterpret_cast<uint32_t*>(&h);
}

__global__ __launch_bounds__(256, 5) void conv3x3_hmma_fp16_kernel(
    const float* __restrict__ x,
    const float* __restrict__ Wt,   // [16co][16cin][3][3]
    float* __restrict__ out)
{
    extern __shared__ __align__(128) char smem[];
    const int tid = threadIdx.x, wid = tid >> 5, lid = tid & 31;
    const int w0 = blockIdx.x * TW, h0 = blockIdx.y * TH, b = blockIdx.z;

    // ---- stage X: one thread per pixel, 16 LDG.32 -> 2x STS.128 (fp16) ----
    const float* xb = x + (size_t)b * 16 * H_ * Wd_;
    for (int p = tid; p < NR * RW; p += 256) {
        const int row = p / RW, px = p - row * RW;
        const int ih = h0 - 1 + row, iw = w0 - 1 + px;
        const bool valid = ((unsigned)ih < (unsigned)H_) &&
                           ((unsigned)iw < (unsigned)Wd_);
        float v[16];
#pragma unroll
        for (int c = 0; c < 16; c++)
            v[c] = valid ? xb[((size_t)c * H_ + ih) * Wd_ + iw] : 0.f;

        uint4 hA = make_uint4(pkf(v[0], v[1]),  pkf(v[2], v[3]),
                              pkf(v[4], v[5]),  pkf(v[6], v[7]));
        uint4 hB = make_uint4(pkf(v[8], v[9]),  pkf(v[10], v[11]),
                              pkf(v[12], v[13]), pkf(v[14], v[15]));
        char* s = smem + p * SLOT;
        *(uint4*)(s)      = hA;
        *(uint4*)(s + 16) = hB;
    }

    // ---- weights -> per-lane B fragments: [tap][nc][lane] uint2 ----
    // B frag (m16n8k16 col): b.x = B[k0..k0+1][n], b.y = B[k0+8..k0+9][n],
    //   n = lane>>2 (+8*nc), k0 = 2*(lane&3).
    uint2* wf = (uint2*)(smem + WF_OFF);
    for (int c = wid; c < 18; c += 8) {
        int tap = c >> 1, nc = c & 1;
        int co = nc * 8 + (lid >> 2);
        int k0 = 2 * (lid & 3);
        float w00 = Wt[co * 144 + k0 * 9 + tap];
        float w01 = Wt[co * 144 + (k0 + 1) * 9 + tap];
        float w10 = Wt[co * 144 + (k0 + 8) * 9 + tap];
        float w11 = Wt[co * 144 + (k0 + 9) * 9 + tap];
        wf[(tap * 2 + nc) * 32 + lid] = make_uint2(pkf(w00, w01), pkf(w10, w11));
    }
    __syncthreads();

    // ---- compute: warp -> (row r, w-segment); tap outer, 4 m16 tiles inner ----
    const uint32_t xs = smem_u32(smem);
    const int r = wid >> 1, wseg = wid & 1;

    const int mat  = lid >> 3;
    const int arow = (mat & 1) * 8 + (lid & 7);
    const int kofs = (mat >> 1) * 16;

    float acc[4][2][4];
#pragma unroll
    for (int mt = 0; mt < 4; mt++)
#pragma unroll
        for (int nc = 0; nc < 2; nc++)
#pragma unroll
            for (int i = 0; i < 4; i++) acc[mt][nc][i] = 0.f;

#pragma unroll
    for (int kh = 0; kh < 3; kh++) {
#pragma unroll
        for (int kw = 0; kw < 3; kw++) {
            const int tap = kh * 3 + kw;
            const uint2 b0 = wf[(tap * 2 + 0) * 32 + lid];
            const uint2 b1 = wf[(tap * 2 + 1) * 32 + lid];
            const uint32_t abase =
                xs + (uint32_t)(((r + kh) * RW + wseg * 64 + kw + arow) * SLOT + kofs);
#pragma unroll
            for (int mt = 0; mt < 4; mt++) {
                uint32_t a[4];
                ldm4(a, abase + (uint32_t)(mt * 16 * SLOT));
                mma16816(acc[mt][0], a, b0);
                mma16816(acc[mt][1], a, b1);
            }
        }
    }

    // ---- epilogue ----
    const int h = h0 + r;
    const int rowp = lid >> 2, col2 = 2 * (lid & 3);
#pragma unroll
    for (int mt = 0; mt < 4; mt++) {
        const int w = w0 + wseg * 64 + mt * 16 + rowp;
#pragma unroll
        for (int nc = 0; nc < 2; nc++) {
            int co = nc * 8 + col2;
            size_t base = (((size_t)b * 16 + co) * H_ + h) * Wd_ + w;
            out[base]                        = acc[mt][nc][0];
            out[base + (size_t)H_ * Wd_]     = acc[mt][nc][1];
            out[base + 8]                    = acc[mt][nc][2];
            out[base + (size_t)H_ * Wd_ + 8] = acc[mt][nc][3];
        }
    }
}

extern "C" void kernel_launch(void* const* d_in, const int* in_sizes, int n_in,
                              void* d_out, int out_size) {
    const float* x  = (const float*)d_in[0];
    const float* Wt = (const float*)d_in[1];
    if (n_in >= 2 && in_sizes[0] == 16 * 16 * 9) {
        const float* tmp = x; x = Wt; Wt = tmp;
    }
    float* out = (float*)d_out;

    cudaFuncSetAttribute(conv3x3_hmma_fp16_kernel,
                         cudaFuncAttributeMaxDynamicSharedMemorySize, SMEM_BYTES);
    dim3 grid(Wd_ / TW, H_ / TH, B_);
    conv3x3_hmma_fp16_kernel<<<grid, 256, SMEM_BYTES>>>(x, Wt, out);
}

// round 13
// speedup vs baseline: 3.5120x; 1.1928x over previous
#include <cuda_runtime.h>
#include <cuda_fp16.h>
#include <cstdint>

// 3x3 s1 p1 conv, NCHW fp32, B=8 C=16 H=W=1024.
// Warp-level HMMA (mma.sync m16n8k16 f16, fp32 accum) implicit GEMM, fp16 single-pass.
// R11: load A fragments only at kw=0 alignment (4 ldm4 + 1 boundary ldm2 per kh);
// kw=1 / kw=2 fragments derived in-register via lane shuffles (M-shift by 1/2).
// X staged in smem: [row][pixel][16cin fp16 = 32B], slot 48B (conflict-free ldmatrix).

#define B_   8
#define H_   1024
#define Wd_  1024
#define TH   4
#define TW   128
#define NR   (TH + 2)     // 6 input rows
#define RW   138          // 130 needed + 8 slack so boundary ldm2 stays in-bounds
#define SLOT 48           // bytes per pixel slot (32 used)
#define XS_BYTES (NR * RW * SLOT)          // 39744
#define WF_OFF   XS_BYTES
#define WF_BYTES (9 * 2 * 32 * 8)          // 4608 (tap,nc,lane -> uint2)
#define SMEM_BYTES (XS_BYTES + WF_BYTES)   // 44352

__device__ __forceinline__ uint32_t smem_u32(const void* p) {
    uint32_t a;
    asm("{ .reg .u64 t; cvta.to.shared.u64 t, %1; cvt.u32.u64 %0, t; }"
        : "=r"(a) : "l"(p));
    return a;
}

__device__ __forceinline__ void ldm4(uint32_t* a, uint32_t addr) {
    asm volatile("ldmatrix.sync.aligned.m8n8.x4.shared.b16 {%0,%1,%2,%3}, [%4];"
                 : "=r"(a[0]), "=r"(a[1]), "=r"(a[2]), "=r"(a[3]) : "r"(addr));
}

__device__ __forceinline__ void ldm2(uint32_t& r0, uint32_t& r1, uint32_t addr) {
    asm volatile("ldmatrix.sync.aligned.m8n8.x2.shared.b16 {%0,%1}, [%2];"
                 : "=r"(r0), "=r"(r1) : "r"(addr));
}

__device__ __forceinline__ void mma16816(float* d, const uint32_t* a, uint2 b) {
    asm volatile(
        "mma.sync.aligned.m16n8k16.row.col.f32.f16.f16.f32 "
        "{%0,%1,%2,%3}, {%4,%5,%6,%7}, {%8,%9}, {%0,%1,%2,%3};"
        : "+f"(d[0]), "+f"(d[1]), "+f"(d[2]), "+f"(d[3])
        : "r"(a[0]), "r"(a[1]), "r"(a[2]), "r"(a[3]), "r"(b.x), "r"(b.y));
}

__device__ __forceinline__ uint32_t pkf(float a, float b) {
    __half2 h = __floats2half2_rn(a, b);
    return *reinterpret_cast<uint32_t*>(&h);
}

// Derive A-fragment M-shifted by d pixels (d = 1 or 2).
// Fragment regs: f0 (rows g, k0..7), f1 (rows g+8), f2 (rows g, k8..15), f3 (rows g+8).
// Shifted row g comes from lane l+4d; top d row-groups wrap: f0'<-f1, f1'<-next.f0.
// Note l-28 == l+4 (mod 32) and l-24 == l+8 (mod 32): single source lane per shift.
__device__ __forceinline__ void shiftfrag(const uint32_t* C, uint32_t nf0, uint32_t nf2,
                                          uint32_t* O, int lid, int d) {
    const int s = (lid + 4 * d) & 31;
    const bool in = lid < (32 - 4 * d);
    uint32_t c0 = __shfl_sync(0xFFFFFFFFu, C[0], s);
    uint32_t c1 = __shfl_sync(0xFFFFFFFFu, C[1], s);
    uint32_t c2 = __shfl_sync(0xFFFFFFFFu, C[2], s);
    uint32_t c3 = __shfl_sync(0xFFFFFFFFu, C[3], s);
    uint32_t n0 = __shfl_sync(0xFFFFFFFFu, nf0, s);
    uint32_t n2 = __shfl_sync(0xFFFFFFFFu, nf2, s);
    O[0] = in ? c0 : c1;
    O[1] = in ? c1 : n0;
    O[2] = in ? c2 : c3;
    O[3] = in ? c3 : n2;
}

__global__ __launch_bounds__(256, 4) void conv3x3_hmma_fp16_kernel(
    const float* __restrict__ x,
    const float* __restrict__ Wt,   // [16co][16cin][3][3]
    float* __restrict__ out)
{
    extern __shared__ __align__(128) char smem[];
    const int tid = threadIdx.x, wid = tid >> 5, lid = tid & 31;
    const int w0 = blockIdx.x * TW, h0 = blockIdx.y * TH, b = blockIdx.z;

    // ---- stage X: one thread per pixel, 16 LDG.32 -> 2x STS.128 (fp16) ----
    const float* xb = x + (size_t)b * 16 * H_ * Wd_;
    for (int p = tid; p < NR * RW; p += 256) {
        const int row = p / RW, px = p - row * RW;
        const int ih = h0 - 1 + row, iw = w0 - 1 + px;
        const bool valid = ((unsigned)ih < (unsigned)H_) &&
                           ((unsigned)iw < (unsigned)Wd_);
        float v[16];
#pragma unroll
        for (int c = 0; c < 16; c++)
            v[c] = valid ? xb[((size_t)c * H_ + ih) * Wd_ + iw] : 0.f;

        uint4 hA = make_uint4(pkf(v[0], v[1]),  pkf(v[2], v[3]),
                              pkf(v[4], v[5]),  pkf(v[6], v[7]));
        uint4 hB = make_uint4(pkf(v[8], v[9]),  pkf(v[10], v[11]),
                              pkf(v[12], v[13]), pkf(v[14], v[15]));
        char* s = smem + p * SLOT;
        *(uint4*)(s)      = hA;
        *(uint4*)(s + 16) = hB;
    }

    // ---- weights -> per-lane B fragments: [tap][nc][lane] uint2 ----
    uint2* wf = (uint2*)(smem + WF_OFF);
    for (int c = wid; c < 18; c += 8) {
        int tap = c >> 1, nc = c & 1;
        int co = nc * 8 + (lid >> 2);
        int k0 = 2 * (lid & 3);
        float w00 = Wt[co * 144 + k0 * 9 + tap];
        float w01 = Wt[co * 144 + (k0 + 1) * 9 + tap];
        float w10 = Wt[co * 144 + (k0 + 8) * 9 + tap];
        float w11 = Wt[co * 144 + (k0 + 9) * 9 + tap];
        wf[(tap * 2 + nc) * 32 + lid] = make_uint2(pkf(w00, w01), pkf(w10, w11));
    }
    __syncthreads();

    // ---- compute ----
    const uint32_t xs = smem_u32(smem);
    const int r = wid >> 1, wseg = wid & 1;

    // ldmatrix x4 lane addressing (16 rows x 32B at stride SLOT)
    const int mat  = lid >> 3;
    const int arow = (mat & 1) * 8 + (lid & 7);
    const int kofs = (mat >> 1) * 16;

    float acc[4][2][4];
#pragma unroll
    for (int mt = 0; mt < 4; mt++)
#pragma unroll
        for (int nc = 0; nc < 2; nc++)
#pragma unroll
            for (int i = 0; i < 4; i++) acc[mt][nc][i] = 0.f;

#pragma unroll
    for (int kh = 0; kh < 3; kh++) {
        // A tiles at kw=0 alignment: slot = ol0 + mt*16 + row  (ol0 = wseg*64)
        const uint32_t rowbase = (uint32_t)((r + kh) * RW + wseg * 64);
        uint32_t C[4][4];
#pragma unroll
        for (int mt = 0; mt < 4; mt++)
            ldm4(C[mt], xs + (rowbase + mt * 16 + arow) * SLOT + kofs);
        // right boundary tile row0/1: slots ol0+64 .. +71 (8 rows, 2 k-halves)
        uint32_t R0, R1;
        ldm2(R0, R1, xs + (rowbase + 64 + (lid & 7)) * SLOT + ((lid >> 3) & 1) * 16);

        const uint2 bA0 = wf[((kh * 3 + 0) * 2 + 0) * 32 + lid];
        const uint2 bA1 = wf[((kh * 3 + 0) * 2 + 1) * 32 + lid];
        const uint2 bB0 = wf[((kh * 3 + 1) * 2 + 0) * 32 + lid];
        const uint2 bB1 = wf[((kh * 3 + 1) * 2 + 1) * 32 + lid];
        const uint2 bC0 = wf[((kh * 3 + 2) * 2 + 0) * 32 + lid];
        const uint2 bC1 = wf[((kh * 3 + 2) * 2 + 1) * 32 + lid];

#pragma unroll
        for (int mt = 0; mt < 4; mt++) {
            // kw = 0 : direct
            mma16816(acc[mt][0], C[mt], bA0);
            mma16816(acc[mt][1], C[mt], bA1);

            const uint32_t nf0 = (mt < 3) ? C[mt + 1][0] : R0;
            const uint32_t nf2 = (mt < 3) ? C[mt + 1][2] : R1;
            uint32_t S[4];
            // kw = 1 : shift by 1 pixel
            shiftfrag(C[mt], nf0, nf2, S, lid, 1);
            mma16816(acc[mt][0], S, bB0);
            mma16816(acc[mt][1], S, bB1);
            // kw = 2 : shift by 2 pixels
            shiftfrag(C[mt], nf0, nf2, S, lid, 2);
            mma16816(acc[mt][0], S, bC0);
            mma16816(acc[mt][1], S, bC1);
        }
    }

    // ---- epilogue ----
    const int h = h0 + r;
    const int rowp = lid >> 2, col2 = 2 * (lid & 3);
#pragma unroll
    for (int mt = 0; mt < 4; mt++) {
        const int w = w0 + wseg * 64 + mt * 16 + rowp;
#pragma unroll
        for (int nc = 0; nc < 2; nc++) {
            int co = nc * 8 + col2;
            size_t base = (((size_t)b * 16 + co) * H_ + h) * Wd_ + w;
            out[base]                        = acc[mt][nc][0];
            out[base + (size_t)H_ * Wd_]     = acc[mt][nc][1];
            out[base + 8]                    = acc[mt][nc][2];
            out[base + (size_t)H_ * Wd_ + 8] = acc[mt][nc][3];
        }
    }
}

extern "C" void kernel_launch(void* const* d_in, const int* in_sizes, int n_in,
                              void* d_out, int out_size) {
    const float* x  = (const float*)d_in[0];
    const float* Wt = (const float*)d_in[1];
    if (n_in >= 2 && in_sizes[0] == 16 * 16 * 9) {
        const float* tmp = x; x = Wt; Wt = tmp;
    }
    float* out = (float*)d_out;

    cudaFuncSetAttribute(conv3x3_hmma_fp16_kernel,
                         cudaFuncAttributeMaxDynamicSharedMemorySize, SMEM_BYTES);
    dim3 grid(Wd_ / TW, H_ / TH, B_);
    conv3x3_hmma_fp16_kernel<<<grid, 256, SMEM_BYTES>>>(x, Wt, out);
}

// round 14
// speedup vs baseline: 3.8384x; 1.0930x over previous
#include <cuda_runtime.h>
#include <cuda_fp16.h>
#include <cstdint>

// 3x3 s1 p1 conv, NCHW fp32, B=8 C=16 H=W=1024.
// HMMA (mma.sync m16n8k16 f16, fp32 accum) implicit GEMM, fp16 single-pass.
// R11: kw=1/2 A-fragments derived via lane shuffles (only kw=0 ldmatrix loads).
// R14: epilogue transposed through smem -> fully coalesced STG.128;
//      B-fragments packed as uint4 (one LDS.128 per tap).

#define B_   8
#define H_   1024
#define Wd_  1024
#define TH   4
#define TW   128
#define NR   (TH + 2)     // 6 input rows
#define RW   138          // 130 needed + slack so boundary ldm2 stays in-bounds
#define SLOT 48           // bytes per pixel slot (32 used)
#define XS_BYTES (NR * RW * SLOT)          // 39744
#define WF_OFF   XS_BYTES
#define WF_BYTES (9 * 32 * 16)             // 4608: [tap][lane] -> uint4
#define SMEM_BYTES (XS_BYTES + WF_BYTES)   // 44352
#define EPW 132                            // padded floats per (r,co) row

__device__ __forceinline__ uint32_t smem_u32(const void* p) {
    uint32_t a;
    asm("{ .reg .u64 t; cvta.to.shared.u64 t, %1; cvt.u32.u64 %0, t; }"
        : "=r"(a) : "l"(p));
    return a;
}

__device__ __forceinline__ void ldm4(uint32_t* a, uint32_t addr) {
    asm volatile("ldmatrix.sync.aligned.m8n8.x4.shared.b16 {%0,%1,%2,%3}, [%4];"
                 : "=r"(a[0]), "=r"(a[1]), "=r"(a[2]), "=r"(a[3]) : "r"(addr));
}

__device__ __forceinline__ void ldm2(uint32_t& r0, uint32_t& r1, uint32_t addr) {
    asm volatile("ldmatrix.sync.aligned.m8n8.x2.shared.b16 {%0,%1}, [%2];"
                 : "=r"(r0), "=r"(r1) : "r"(addr));
}

__device__ __forceinline__ void mma16816(float* d, const uint32_t* a, uint32_t bx, uint32_t by) {
    asm volatile(
        "mma.sync.aligned.m16n8k16.row.col.f32.f16.f16.f32 "
        "{%0,%1,%2,%3}, {%4,%5,%6,%7}, {%8,%9}, {%0,%1,%2,%3};"
        : "+f"(d[0]), "+f"(d[1]), "+f"(d[2]), "+f"(d[3])
        : "r"(a[0]), "r"(a[1]), "r"(a[2]), "r"(a[3]), "r"(bx), "r"(by));
}

__device__ __forceinline__ uint32_t pkf(float a, float b) {
    __half2 h = __floats2half2_rn(a, b);
    return *reinterpret_cast<uint32_t*>(&h);
}

// Derive A-fragment M-shifted by d pixels (d = 1 or 2); see R11 comment.
__device__ __forceinline__ void shiftfrag(const uint32_t* C, uint32_t nf0, uint32_t nf2,
                                          uint32_t* O, int lid, int d) {
    const int s = (lid + 4 * d) & 31;
    const bool in = lid < (32 - 4 * d);
    uint32_t c0 = __shfl_sync(0xFFFFFFFFu, C[0], s);
    uint32_t c1 = __shfl_sync(0xFFFFFFFFu, C[1], s);
    uint32_t c2 = __shfl_sync(0xFFFFFFFFu, C[2], s);
    uint32_t c3 = __shfl_sync(0xFFFFFFFFu, C[3], s);
    uint32_t n0 = __shfl_sync(0xFFFFFFFFu, nf0, s);
    uint32_t n2 = __shfl_sync(0xFFFFFFFFu, nf2, s);
    O[0] = in ? c0 : c1;
    O[1] = in ? c1 : n0;
    O[2] = in ? c2 : c3;
    O[3] = in ? c3 : n2;
}

__global__ __launch_bounds__(256, 4) void conv3x3_hmma_fp16_kernel(
    const float* __restrict__ x,
    const float* __restrict__ Wt,   // [16co][16cin][3][3]
    float* __restrict__ out)
{
    extern __shared__ __align__(128) char smem[];
    const int tid = threadIdx.x, wid = tid >> 5, lid = tid & 31;
    const int w0 = blockIdx.x * TW, h0 = blockIdx.y * TH, b = blockIdx.z;

    // ---- stage X: one thread per pixel, 16 LDG.32 -> 2x STS.128 (fp16) ----
    const float* xb = x + (size_t)b * 16 * H_ * Wd_;
    for (int p = tid; p < NR * RW; p += 256) {
        const int row = p / RW, px = p - row * RW;
        const int ih = h0 - 1 + row, iw = w0 - 1 + px;
        const bool valid = ((unsigned)ih < (unsigned)H_) &&
                           ((unsigned)iw < (unsigned)Wd_);
        float v[16];
#pragma unroll
        for (int c = 0; c < 16; c++)
            v[c] = valid ? xb[((size_t)c * H_ + ih) * Wd_ + iw] : 0.f;

        uint4 hA = make_uint4(pkf(v[0], v[1]),  pkf(v[2], v[3]),
                              pkf(v[4], v[5]),  pkf(v[6], v[7]));
        uint4 hB = make_uint4(pkf(v[8], v[9]),  pkf(v[10], v[11]),
                              pkf(v[12], v[13]), pkf(v[14], v[15]));
        char* s = smem + p * SLOT;
        *(uint4*)(s)      = hA;
        *(uint4*)(s + 16) = hB;
    }

    // ---- weights -> per-lane B fragments: [tap][lane] -> uint4 (nc0 | nc1) ----
    uint4* wf = (uint4*)(smem + WF_OFF);
    for (int tap = wid; tap < 9; tap += 8) {
        int k0 = 2 * (lid & 3);
        uint32_t q[2];
#pragma unroll
        for (int nc = 0; nc < 2; nc++) {
            int co = nc * 8 + (lid >> 2);
            float w00 = Wt[co * 144 + k0 * 9 + tap];
            float w01 = Wt[co * 144 + (k0 + 1) * 9 + tap];
            float w10 = Wt[co * 144 + (k0 + 8) * 9 + tap];
            float w11 = Wt[co * 144 + (k0 + 9) * 9 + tap];
            q[0] = pkf(w00, w01); q[1] = pkf(w10, w11);
            if (nc == 0) { wf[tap * 32 + lid].x = q[0]; wf[tap * 32 + lid].y = q[1]; }
            else         { wf[tap * 32 + lid].z = q[0]; wf[tap * 32 + lid].w = q[1]; }
        }
    }
    __syncthreads();

    // ---- compute ----
    const uint32_t xs = smem_u32(smem);
    const int r = wid >> 1, wseg = wid & 1;

    const int mat  = lid >> 3;
    const int arow = (mat & 1) * 8 + (lid & 7);
    const int kofs = (mat >> 1) * 16;

    float acc[4][2][4];
#pragma unroll
    for (int mt = 0; mt < 4; mt++)
#pragma unroll
        for (int nc = 0; nc < 2; nc++)
#pragma unroll
            for (int i = 0; i < 4; i++) acc[mt][nc][i] = 0.f;

#pragma unroll
    for (int kh = 0; kh < 3; kh++) {
        const uint32_t rowbase = (uint32_t)((r + kh) * RW + wseg * 64);
        uint32_t C[4][4];
#pragma unroll
        for (int mt = 0; mt < 4; mt++)
            ldm4(C[mt], xs + (rowbase + mt * 16 + arow) * SLOT + kofs);
        uint32_t R0, R1;
        ldm2(R0, R1, xs + (rowbase + 64 + (lid & 7)) * SLOT + ((lid >> 3) & 1) * 16);

        const uint4 bA = wf[(kh * 3 + 0) * 32 + lid];
        const uint4 bB = wf[(kh * 3 + 1) * 32 + lid];
        const uint4 bC = wf[(kh * 3 + 2) * 32 + lid];

#pragma unroll
        for (int mt = 0; mt < 4; mt++) {
            mma16816(acc[mt][0], C[mt], bA.x, bA.y);
            mma16816(acc[mt][1], C[mt], bA.z, bA.w);

            const uint32_t nf0 = (mt < 3) ? C[mt + 1][0] : R0;
            const uint32_t nf2 = (mt < 3) ? C[mt + 1][2] : R1;
            uint32_t S[4];
            shiftfrag(C[mt], nf0, nf2, S, lid, 1);
            mma16816(acc[mt][0], S, bB.x, bB.y);
            mma16816(acc[mt][1], S, bB.z, bB.w);
            shiftfrag(C[mt], nf0, nf2, S, lid, 2);
            mma16816(acc[mt][0], S, bC.x, bC.y);
            mma16816(acc[mt][1], S, bC.z, bC.w);
        }
    }

    // ---- epilogue: transpose through smem, coalesced STG.128 ----
    __syncthreads();   // X staging dead; reuse [0, 33792) as [r][co][EPW] floats
    float* ep = (float*)smem;
    {
        const int rowp = lid >> 2, col2 = 2 * (lid & 3);
#pragma unroll
        for (int mt = 0; mt < 4; mt++) {
            const int wloc = wseg * 64 + mt * 16 + rowp;
#pragma unroll
            for (int nc = 0; nc < 2; nc++) {
                const int co = nc * 8 + col2;
                float* e = ep + (r * 16 + co) * EPW + wloc;
                e[0]       = acc[mt][nc][0];
                e[EPW]     = acc[mt][nc][1];   // co+1
                e[8]       = acc[mt][nc][2];
                e[EPW + 8] = acc[mt][nc][3];
            }
        }
    }
    __syncthreads();
    // drain: warp -> 8 (r,co) rows; lane -> float4 at w = 4*lid
    {
#pragma unroll
        for (int i = 0; i < 8; i++) {
            const int pr = wid * 8 + i;           // 0..63
            const int r2 = pr >> 4, co = pr & 15;
            float4 v = *(float4*)(ep + (r2 * 16 + co) * EPW + 4 * lid);
            *(float4*)(out + (((size_t)b * 16 + co) * H_ + (h0 + r2)) * Wd_ +
                       w0 + 4 * lid) = v;
        }
    }
}

extern "C" void kernel_launch(void* const* d_in, const int* in_sizes, int n_in,
                              void* d_out, int out_size) {
    const float* x  = (const float*)d_in[0];
    const float* Wt = (const float*)d_in[1];
    if (n_in >= 2 && in_sizes[0] == 16 * 16 * 9) {
        const float* tmp = x; x = Wt; Wt = tmp;
    }
    float* out = (float*)d_out;

    cudaFuncSetAttribute(conv3x3_hmma_fp16_kernel,
                         cudaFuncAttributeMaxDynamicSharedMemorySize, SMEM_BYTES);
    dim3 grid(Wd_ / TW, H_ / TH, B_);
    conv3x3_hmma_fp16_kernel<<<grid, 256, SMEM_BYTES>>>(x, Wt, out);
}

// round 16
// speedup vs baseline: 3.9118x; 1.0191x over previous
#include <cuda_runtime.h>
#include <cuda_fp16.h>
#include <cstdint>

// 3x3 s1 p1 conv, NCHW fp32, B=8 C=16 H=W=1024.
// HMMA (mma.sync m16n8k16 f16, fp32 accum) implicit GEMM, fp16 single-pass.
// R11: kw=1/2 A-fragments derived via lane shuffles (only kw=0 ldmatrix loads).
// R14: smem-transposed epilogue (coalesced STG.128); uint4 B-fragments.
// R15: source-side pre-selected shifts (4 SHFL instead of 6); TH=8 / 512-thr CTA
//      (halo amplification 1.5x -> 1.25x).

#define B_   8
#define H_   1024
#define Wd_  1024
#define TH   8
#define TW   128
#define NT   512
#define NR   (TH + 2)     // 10 input rows
#define RW   138          // 130 needed + slack so boundary ldm2 stays in-bounds
#define SLOT 48           // bytes per pixel slot (32 used)
#define XS_BYTES (NR * RW * SLOT)          // 66240
#define WF_OFF   XS_BYTES
#define WF_BYTES (9 * 32 * 16)             // 4608: [tap][lane] -> uint4
#define SMEM_BYTES (XS_BYTES + WF_BYTES)   // 70848
#define EPW 132                            // padded floats per (r,co) row

__device__ __forceinline__ uint32_t smem_u32(const void* p) {
    uint32_t a;
    asm("{ .reg .u64 t; cvta.to.shared.u64 t, %1; cvt.u32.u64 %0, t; }"
        : "=r"(a) : "l"(p));
    return a;
}

__device__ __forceinline__ void ldm4(uint32_t* a, uint32_t addr) {
    asm volatile("ldmatrix.sync.aligned.m8n8.x4.shared.b16 {%0,%1,%2,%3}, [%4];"
                 : "=r"(a[0]), "=r"(a[1]), "=r"(a[2]), "=r"(a[3]) : "r"(addr));
}

__device__ __forceinline__ void ldm2(uint32_t& r0, uint32_t& r1, uint32_t addr) {
    asm volatile("ldmatrix.sync.aligned.m8n8.x2.shared.b16 {%0,%1}, [%2];"
                 : "=r"(r0), "=r"(r1) : "r"(addr));
}

__device__ __forceinline__ void mma16816(float* d, const uint32_t* a, uint32_t bx, uint32_t by) {
    asm volatile(
        "mma.sync.aligned.m16n8k16.row.col.f32.f16.f16.f32 "
        "{%0,%1,%2,%3}, {%4,%5,%6,%7}, {%8,%9}, {%0,%1,%2,%3};"
        : "+f"(d[0]), "+f"(d[1]), "+f"(d[2]), "+f"(d[3])
        : "r"(a[0]), "r"(a[1]), "r"(a[2]), "r"(a[3]), "r"(bx), "r"(by));
}

__device__ __forceinline__ uint32_t pkf(float a, float b) {
    __half2 h = __floats2half2_rn(a, b);
    return *reinterpret_cast<uint32_t*>(&h);
}

// A-fragment M-shift by d pixels (d=1,2). Destination lane l sources from lane
// s=(l+4d)&31; dest is in the wrap case iff s<4d. So the SOURCE pre-selects the
// value its unique destination needs (4 SELP on alu pipe), then 4 SHFL total.
__device__ __forceinline__ void shiftfrag(const uint32_t* C, uint32_t nf0, uint32_t nf2,
                                          uint32_t* O, int lid, int d) {
    const int s = (lid + 4 * d) & 31;
    const bool hi = lid >= 4 * d;     // this lane's role as a SOURCE
    uint32_t t0 = hi ? C[0] : C[1];
    uint32_t t1 = hi ? C[1] : nf0;
    uint32_t t2 = hi ? C[2] : C[3];
    uint32_t t3 = hi ? C[3] : nf2;
    O[0] = __shfl_sync(0xFFFFFFFFu, t0, s);
    O[1] = __shfl_sync(0xFFFFFFFFu, t1, s);
    O[2] = __shfl_sync(0xFFFFFFFFu, t2, s);
    O[3] = __shfl_sync(0xFFFFFFFFu, t3, s);
}

__global__ __launch_bounds__(NT, 2) void conv3x3_hmma_fp16_kernel(
    const float* __restrict__ x,
    const float* __restrict__ Wt,   // [16co][16cin][3][3]
    float* __restrict__ out)
{
    extern __shared__ __align__(128) char smem[];
    const int tid = threadIdx.x, wid = tid >> 5, lid = tid & 31;
    const int w0 = blockIdx.x * TW, h0 = blockIdx.y * TH, b = blockIdx.z;

    // ---- stage X: one thread per pixel, 16 LDG.32 -> 2x STS.128 (fp16) ----
    const float* xb = x + (size_t)b * 16 * H_ * Wd_;
    for (int p = tid; p < NR * RW; p += NT) {
        const int row = p / RW, px = p - row * RW;
        const int ih = h0 - 1 + row, iw = w0 - 1 + px;
        const bool valid = ((unsigned)ih < (unsigned)H_) &&
                           ((unsigned)iw < (unsigned)Wd_);
        float v[16];
#pragma unroll
        for (int c = 0; c < 16; c++)
            v[c] = valid ? xb[((size_t)c * H_ + ih) * Wd_ + iw] : 0.f;

        uint4 hA = make_uint4(pkf(v[0], v[1]),  pkf(v[2], v[3]),
                              pkf(v[4], v[5]),  pkf(v[6], v[7]));
        uint4 hB = make_uint4(pkf(v[8], v[9]),  pkf(v[10], v[11]),
                              pkf(v[12], v[13]), pkf(v[14], v[15]));
        char* s = smem + p * SLOT;
        *(uint4*)(s)      = hA;
        *(uint4*)(s + 16) = hB;
    }

    // ---- weights -> per-lane B fragments: [tap][lane] -> uint4 (nc0 | nc1) ----
    uint4* wf = (uint4*)(smem + WF_OFF);
    if (wid < 9) {
        const int tap = wid;
        int k0 = 2 * (lid & 3);
        uint4 q;
        {
            int co = (lid >> 2);
            q.x = pkf(Wt[co * 144 + k0 * 9 + tap], Wt[co * 144 + (k0 + 1) * 9 + tap]);
            q.y = pkf(Wt[co * 144 + (k0 + 8) * 9 + tap], Wt[co * 144 + (k0 + 9) * 9 + tap]);
            co += 8;
            q.z = pkf(Wt[co * 144 + k0 * 9 + tap], Wt[co * 144 + (k0 + 1) * 9 + tap]);
            q.w = pkf(Wt[co * 144 + (k0 + 8) * 9 + tap], Wt[co * 144 + (k0 + 9) * 9 + tap]);
        }
        wf[tap * 32 + lid] = q;
    }
    __syncthreads();

    // ---- compute: warp -> (row r, w-segment); 16 warps = 8 rows x 2 segs ----
    const uint32_t xs = smem_u32(smem);
    const int r = wid >> 1, wseg = wid & 1;

    const int mat  = lid >> 3;
    const int arow = (mat & 1) * 8 + (lid & 7);
    const int kofs = (mat >> 1) * 16;

    float acc[4][2][4];
#pragma unroll
    for (int mt = 0; mt < 4; mt++)
#pragma unroll
        for (int nc = 0; nc < 2; nc++)
#pragma unroll
            for (int i = 0; i < 4; i++) acc[mt][nc][i] = 0.f;

#pragma unroll
    for (int kh = 0; kh < 3; kh++) {
        const uint32_t rowbase = (uint32_t)((r + kh) * RW + wseg * 64);
        uint32_t C[4][4];
#pragma unroll
        for (int mt = 0; mt < 4; mt++)
            ldm4(C[mt], xs + (rowbase + mt * 16 + arow) * SLOT + kofs);
        uint32_t R0, R1;
        ldm2(R0, R1, xs + (rowbase + 64 + (lid & 7)) * SLOT + ((lid >> 3) & 1) * 16);

        const uint4 bA = wf[(kh * 3 + 0) * 32 + lid];
        const uint4 bB = wf[(kh * 3 + 1) * 32 + lid];
        const uint4 bC = wf[(kh * 3 + 2) * 32 + lid];

#pragma unroll
        for (int mt = 0; mt < 4; mt++) {
            mma16816(acc[mt][0], C[mt], bA.x, bA.y);
            mma16816(acc[mt][1], C[mt], bA.z, bA.w);

            const uint32_t nf0 = (mt < 3) ? C[mt + 1][0] : R0;
            const uint32_t nf2 = (mt < 3) ? C[mt + 1][2] : R1;
            uint32_t S[4];
            shiftfrag(C[mt], nf0, nf2, S, lid, 1);
            mma16816(acc[mt][0], S, bB.x, bB.y);
            mma16816(acc[mt][1], S, bB.z, bB.w);
            shiftfrag(C[mt], nf0, nf2, S, lid, 2);
            mma16816(acc[mt][0], S, bC.x, bC.y);
            mma16816(acc[mt][1], S, bC.z, bC.w);
        }
    }

    // ---- epilogue: transpose through smem, coalesced STG.128 ----
    __syncthreads();   // X staging dead; reuse as [r 8][co 16][EPW] floats
    float* ep = (float*)smem;
    {
        const int rowp = lid >> 2, col2 = 2 * (lid & 3);
#pragma unroll
        for (int mt = 0; mt < 4; mt++) {
            const int wloc = wseg * 64 + mt * 16 + rowp;
#pragma unroll
            for (int nc = 0; nc < 2; nc++) {
                const int co = nc * 8 + col2;
                float* e = ep + (r * 16 + co) * EPW + wloc;
                e[0]       = acc[mt][nc][0];
                e[EPW]     = acc[mt][nc][1];   // co+1
                e[8]       = acc[mt][nc][2];
                e[EPW + 8] = acc[mt][nc][3];
            }
        }
    }
    __syncthreads();
    // drain: warp -> 8 (r,co) rows; lane -> float4 at w = 4*lid
    {
#pragma unroll
        for (int i = 0; i < 8; i++) {
            const int pr = wid * 8 + i;           // 0..127
            const int r2 = pr >> 4, co = pr & 15;
            float4 v = *(float4*)(ep + (r2 * 16 + co) * EPW + 4 * lid);
            *(float4*)(out + (((size_t)b * 16 + co) * H_ + (h0 + r2)) * Wd_ +
                       w0 + 4 * lid) = v;
        }
    }
}

extern "C" void kernel_launch(void* const* d_in, const int* in_sizes, int n_in,
                              void* d_out, int out_size) {
    const float* x  = (const float*)d_in[0];
    const float* Wt = (const float*)d_in[1];
    if (n_in >= 2 && in_sizes[0] == 16 * 16 * 9) {
        const float* tmp = x; x = Wt; Wt = tmp;
    }
    float* out = (float*)d_out;

    cudaFuncSetAttribute(conv3x3_hmma_fp16_kernel,
                         cudaFuncAttributeMaxDynamicSharedMemorySize, SMEM_BYTES);
    dim3 grid(Wd_ / TW, H_ / TH, B_);
    conv3x3_hmma_fp16_kernel<<<grid, NT, SMEM_BYTES>>>(x, Wt, out);
}